// round 13
// baseline (speedup 1.0000x reference)
#include <cuda_runtime.h>
#include <cuda_bf16.h>
#include <mma.h>
#include <math.h>
#include <cstdint>

#define B_    256
#define N_    200
#define FIN   768
#define HID   32
#define NH    8
#define FC    256                 // NH*HID
#define ROWS  (B_*N_)             // 51200
#define ALPHA 0.3f
#define NEGINF (-9e15f)

// attn1 padding
#define NPAD 224   // j padded to 7 chunks of 32
#define MPAD 208   // i padded to 13 m-tiles of 16

// ---------------- scratch (device globals; no allocations allowed) ----------
__device__ float          g_H1[(size_t)ROWS*FC];
__device__ float          g_X2[(size_t)ROWS*FC];
__device__ unsigned       g_mask[(size_t)ROWS*8];
__device__ __nv_bfloat16  g_Wthi[(size_t)FC*FIN];   // W^T hi, [n][k]
__device__ __nv_bfloat16  g_Wtlo[(size_t)FC*FIN];   // W^T lo
__device__ float          g_hs[(size_t)ROWS*2];
__device__ float          g_hp[(size_t)ROWS*2];
__device__ float          g_hq[(size_t)ROWS*HID];
__device__ float          g_s1s[ROWS], g_s2s[ROWS];
__device__ float          g_s1p[ROWS], g_s2p[ROWS];
__device__ float          g_s1qa[ROWS], g_s2qa[ROWS];   // qt partials (feats 0-13)
__device__ float          g_s1qb[ROWS], g_s2qb[ROWS];   // qt partials (feats 14-31)

__device__ __forceinline__ float eluf(float v)  { return v > 0.f ? v : expm1f(v); }
__device__ __forceinline__ float lrelu(float v) { return v > 0.f ? v : ALPHA * v; }

// ---- packed f32x2 helpers ---------------------------------------------------
__device__ __forceinline__ unsigned long long pack2(float lo, float hi) {
    unsigned long long r;
    asm("mov.b64 %0, {%1, %2};" : "=l"(r) : "f"(lo), "f"(hi));
    return r;
}
__device__ __forceinline__ void fma2(unsigned long long& d,
                                     unsigned long long a, unsigned long long b) {
    asm("fma.rn.f32x2 %0, %1, %2, %0;" : "+l"(d) : "l"(a), "l"(b));
}
__device__ __forceinline__ float2 unpack2(unsigned long long v) {
    float2 f;
    asm("mov.b64 {%0, %1}, %2;" : "=f"(f.x), "=f"(f.y) : "l"(v));
    return f;
}

// ---------------- 1) adjacency -> bitmask ------------------------------------
__global__ __launch_bounds__(256) void mask_kernel(const int* __restrict__ adj)
{
    int gw   = (blockIdx.x * blockDim.x + threadIdx.x) >> 5;
    int lane = threadIdx.x & 31;
    if (gw >= ROWS) return;
    const int* row = adj + (size_t)gw * N_;
    unsigned*  dst = g_mask + (size_t)gw * 8;
    #pragma unroll
    for (int w = 0; w < 7; ++w) {
        int j = w * 32 + lane;
        int v = (j < N_) ? (row[j] > 0) : 0;
        unsigned bits = __ballot_sync(0xffffffffu, v);
        if (lane == 0) dst[w] = bits;
    }
}

// ---------------- 1b) W -> W^T bf16 hi/lo ------------------------------------
__global__ __launch_bounds__(256) void wcvt_kernel(const float* __restrict__ Wh)
{
    int k = blockIdx.x;       // 0..767
    int n = threadIdx.x;      // 0..255
    float w = Wh[(size_t)(n >> 5) * FIN * HID + (size_t)k * HID + (n & 31)];
    __nv_bfloat16 h = __float2bfloat16(w);
    g_Wthi[(size_t)n * FIN + k] = h;
    g_Wtlo[(size_t)n * FIN + k] = __float2bfloat16(w - __bfloat162float(h));
}

// ---------------- 2) H1 = feat @ Wcat via wmma bf16-split --------------------
#define ASTR 40
__global__ __launch_bounds__(256) void gemm1_mma_kernel(const float* __restrict__ feat)
{
    using namespace nvcuda;
    __shared__ __align__(16) __nv_bfloat16 sAhi[128*ASTR];
    __shared__ __align__(16) __nv_bfloat16 sAlo[128*ASTR];
    __shared__ __align__(16) __nv_bfloat16 sBhi[128*ASTR];
    __shared__ __align__(16) __nv_bfloat16 sBlo[128*ASTR];

    int tid = threadIdx.x, wid = tid >> 5;
    int blockRow = blockIdx.y * 128, colBase = blockIdx.x * 128;

    int lrow = tid >> 1, lhalf = tid & 1;
    const float* aPtr = feat + (size_t)(blockRow + lrow) * FIN + lhalf * 16;
    const __nv_bfloat16* bhPtr = g_Wthi + (size_t)(colBase + lrow) * FIN + lhalf * 16;
    const __nv_bfloat16* blPtr = g_Wtlo + (size_t)(colBase + lrow) * FIN + lhalf * 16;
    uint32_t sOffA = (uint32_t)(lrow * ASTR + lhalf * 16) * 2;

    int m0 = (wid & 3) * 32, n0 = (wid >> 2) * 64;

    wmma::fragment<wmma::accumulator, 16, 16, 16, float> cf[2][4];
    #pragma unroll
    for (int mt = 0; mt < 2; ++mt)
        #pragma unroll
        for (int nt = 0; nt < 4; ++nt)
            wmma::fill_fragment(cf[mt][nt], 0.f);

    for (int c = 0; c < FIN/32; ++c) {
        int k0 = c * 32;
        {
            const float* ap = aPtr + k0;
            float4 f0 = *(const float4*)(ap);
            float4 f1 = *(const float4*)(ap + 4);
            float4 f2 = *(const float4*)(ap + 8);
            float4 f3 = *(const float4*)(ap + 12);
            uint32_t h[8], l[8];
            float fs[16] = {f0.x,f0.y,f0.z,f0.w, f1.x,f1.y,f1.z,f1.w,
                            f2.x,f2.y,f2.z,f2.w, f3.x,f3.y,f3.z,f3.w};
            #pragma unroll
            for (int q = 0; q < 8; ++q) {
                __nv_bfloat162 hh = __floats2bfloat162_rn(fs[2*q], fs[2*q+1]);
                __nv_bfloat162 ll = __floats2bfloat162_rn(
                    fs[2*q]   - __bfloat162float(hh.x),
                    fs[2*q+1] - __bfloat162float(hh.y));
                h[q] = *(uint32_t*)&hh;
                l[q] = *(uint32_t*)&ll;
            }
            uint4* dH = (uint4*)((char*)sAhi + sOffA);
            uint4* dL = (uint4*)((char*)sAlo + sOffA);
            dH[0] = make_uint4(h[0],h[1],h[2],h[3]);
            dH[1] = make_uint4(h[4],h[5],h[6],h[7]);
            dL[0] = make_uint4(l[0],l[1],l[2],l[3]);
            dL[1] = make_uint4(l[4],l[5],l[6],l[7]);
        }
        {
            const uint4* bh = (const uint4*)(bhPtr + k0);
            const uint4* bl = (const uint4*)(blPtr + k0);
            uint4* dH = (uint4*)((char*)sBhi + sOffA);
            uint4* dL = (uint4*)((char*)sBlo + sOffA);
            dH[0] = bh[0]; dH[1] = bh[1];
            dL[0] = bl[0]; dL[1] = bl[1];
        }
        __syncthreads();

        #pragma unroll
        for (int ks = 0; ks < 32; ks += 16) {
            wmma::fragment<wmma::matrix_a, 16, 16, 16, __nv_bfloat16, wmma::row_major> aH[2], aL[2];
            #pragma unroll
            for (int mt = 0; mt < 2; ++mt) {
                wmma::load_matrix_sync(aH[mt], &sAhi[(m0 + mt*16) * ASTR + ks], ASTR);
                wmma::load_matrix_sync(aL[mt], &sAlo[(m0 + mt*16) * ASTR + ks], ASTR);
            }
            #pragma unroll
            for (int nt = 0; nt < 4; ++nt) {
                wmma::fragment<wmma::matrix_b, 16, 16, 16, __nv_bfloat16, wmma::col_major> bH, bL;
                wmma::load_matrix_sync(bH, &sBhi[(n0 + nt*16) * ASTR + ks], ASTR);
                wmma::load_matrix_sync(bL, &sBlo[(n0 + nt*16) * ASTR + ks], ASTR);
                #pragma unroll
                for (int mt = 0; mt < 2; ++mt) {
                    wmma::mma_sync(cf[mt][nt], aH[mt], bH, cf[mt][nt]);
                    wmma::mma_sync(cf[mt][nt], aH[mt], bL, cf[mt][nt]);
                    wmma::mma_sync(cf[mt][nt], aL[mt], bH, cf[mt][nt]);
                }
            }
        }
        __syncthreads();
    }

    #pragma unroll
    for (int mt = 0; mt < 2; ++mt)
        #pragma unroll
        for (int nt = 0; nt < 4; ++nt) {
            int gm = blockRow + m0 + mt*16;
            int gn = colBase + n0 + nt*16;
            wmma::store_matrix_sync(&g_H1[(size_t)gm * FC + gn], cf[mt][nt],
                                    FC, wmma::mem_row_major);
        }
}

// ---------------- 3) layer-1 attention via wmma (P @ h on tensor cores) ------
// Per (b,h): P[i][j] = softmax prob (pre-normalization), C = P @ h, out = elu(C/l)*bn.
// P built 32 j-cols at a time as bf16 hi/lo; h staged as bf16 hi/lo; 3-term MMA.
// Dynamic smem layout (bytes):
//   hHI [NPAD*32] bf16   @0        14336
//   hLO [NPAD*32] bf16   @14336    14336
//   PHI [MPAD*32] bf16   @28672    13312   (union: sC [MPAD*32] f32 = 26624)
//   PLO [MPAD*32] bf16   @41984    13312
//   s1v[200] f32 @55296, s2v @56096, mv @56896, lv @57696
//   shm[200*7]   @58496 (5600)
//   sa[64]       @64096 (256)      total 64352
#define A1_SMEM 64352
extern __shared__ char a1smem[];
__global__ void attn1_kernel(const float* __restrict__ ah,
                             const float* __restrict__ bn_g,
                             const float* __restrict__ bn_b,
                             const float* __restrict__ bn_m,
                             const float* __restrict__ bn_v)
{
    using namespace nvcuda;
    int b = blockIdx.x >> 3, h = blockIdx.x & 7;
    int tid = threadIdx.x, wid = tid >> 5;
    size_t base = (size_t)b * N_;

    __nv_bfloat16* hHI = (__nv_bfloat16*)(a1smem);
    __nv_bfloat16* hLO = (__nv_bfloat16*)(a1smem + 14336);
    __nv_bfloat16* PHI = (__nv_bfloat16*)(a1smem + 28672);
    __nv_bfloat16* PLO = (__nv_bfloat16*)(a1smem + 41984);
    float*    sC  = (float*)(a1smem + 28672);      // union with PHI+PLO
    float*    s1v = (float*)(a1smem + 55296);
    float*    s2v = (float*)(a1smem + 56096);
    float*    mv  = (float*)(a1smem + 56896);
    float*    lv  = (float*)(a1smem + 57696);
    unsigned* shm = (unsigned*)(a1smem + 58496);
    float*    sa  = (float*)(a1smem + 64096);

    // ---- stage h -> bf16 hi/lo (coalesced), sa, mask -----------------------
    for (int idx = tid; idx < N_*8; idx += 256) {
        int n = idx >> 3, q = idx & 7;
        float4 v = *(const float4*)(g_H1 + (base + n) * FC + h*HID + q*4);
        __nv_bfloat162 h0 = __floats2bfloat162_rn(v.x, v.y);
        __nv_bfloat162 h1 = __floats2bfloat162_rn(v.z, v.w);
        __nv_bfloat162 l0 = __floats2bfloat162_rn(v.x - __bfloat162float(h0.x),
                                                  v.y - __bfloat162float(h0.y));
        __nv_bfloat162 l1 = __floats2bfloat162_rn(v.z - __bfloat162float(h1.x),
                                                  v.w - __bfloat162float(h1.y));
        uint32_t* dH = (uint32_t*)(hHI + n*32 + q*4);
        uint32_t* dL = (uint32_t*)(hLO + n*32 + q*4);
        dH[0] = *(uint32_t*)&h0; dH[1] = *(uint32_t*)&h1;
        dL[0] = *(uint32_t*)&l0; dL[1] = *(uint32_t*)&l1;
    }
    // zero pad rows 200..223
    for (int idx = tid; idx < (NPAD - N_) * 16; idx += 256) {
        ((uint32_t*)(hHI + N_*32))[idx] = 0;
        ((uint32_t*)(hLO + N_*32))[idx] = 0;
    }
    if (tid < 64) sa[tid] = ah[h*64 + tid];
    for (int idx = tid; idx < N_*7; idx += 256)
        shm[idx] = g_mask[(base + idx/7)*8 + idx%7];
    __syncthreads();

    // ---- s1/s2 per row -----------------------------------------------------
    if (tid < N_) {
        float s1 = 0.f, s2 = 0.f;
        #pragma unroll 8
        for (int f = 0; f < HID; ++f) {
            float hv = __bfloat162float(hHI[tid*32 + f]) + __bfloat162float(hLO[tid*32 + f]);
            s1 += hv * sa[f];
            s2 += hv * sa[32 + f];
        }
        s1v[tid] = s1; s2v[tid] = s2;
    }
    __syncthreads();

    // ---- pass 1: per-row m (monotone lrelu trick) --------------------------
    if (tid < N_) {
        float mx = -3.4e38f; unsigned any = 0;
        for (int w = 0; w < 7; ++w) {
            unsigned word = shm[tid*7 + w];
            any |= word;
            int jn = (w == 6) ? 8 : 32;
            #pragma unroll 8
            for (int jj = 0; jj < jn; ++jj)
                if ((word >> jj) & 1) mx = fmaxf(mx, s2v[w*32 + jj]);
        }
        mv[tid] = any ? lrelu(s1v[tid] + mx) : NEGINF;
    }
    __syncthreads();

    // ---- chunked P build + wmma accumulate ---------------------------------
    wmma::fragment<wmma::accumulator, 16, 16, 16, float> cf[2][2];
    int nMt = (wid < 5) ? 2 : 1;    // m-tiles: wid, and wid+8 (13 total)
    #pragma unroll
    for (int mt = 0; mt < 2; ++mt)
        #pragma unroll
        for (int nt = 0; nt < 2; ++nt)
            wmma::fill_fragment(cf[mt][nt], 0.f);

    for (int jc = 0; jc < 7; ++jc) {
        // build P tile [MPAD x 32]
        for (int idx = tid; idx < MPAD*32; idx += 256) {
            int i = idx >> 5, jj = idx & 31, j = jc*32 + jj;
            float p = 0.f;
            if (i < N_ && j < N_) {
                unsigned word = shm[i*7 + (j >> 5)];
                float t = s1v[i] + s2v[j];
                t = t > 0.f ? t : ALPHA * t;
                float e = ((word >> (j & 31)) & 1) ? t : NEGINF;
                p = __expf(e - mv[i]);
            }
            __nv_bfloat16 ph = __float2bfloat16(p);
            PHI[idx] = ph;
            PLO[idx] = __float2bfloat16(p - __bfloat162float(ph));
        }
        __syncthreads();

        // per-row l partial (from hi+lo, j<200 only)
        if (tid < N_) {
            int jlim = (jc == 6) ? 8 : 32;
            float s = 0.f;
            for (int jj = 0; jj < jlim; ++jj)
                s += __bfloat162float(PHI[tid*32 + jj]) + __bfloat162float(PLO[tid*32 + jj]);
            lv[tid] = (jc == 0 ? 0.f : lv[tid]) + s;
        }

        // MMA: C += Phi*hhi + Phi*hlo + Plo*hhi
        #pragma unroll
        for (int mt = 0; mt < 2; ++mt) {
            if (mt >= nMt) break;
            int mrow = (wid + mt*8) * 16;
            #pragma unroll
            for (int ks = 0; ks < 2; ++ks) {
                wmma::fragment<wmma::matrix_a, 16, 16, 16, __nv_bfloat16, wmma::row_major> aH, aL;
                wmma::load_matrix_sync(aH, &PHI[mrow*32 + ks*16], 32);
                wmma::load_matrix_sync(aL, &PLO[mrow*32 + ks*16], 32);
                #pragma unroll
                for (int nt = 0; nt < 2; ++nt) {
                    wmma::fragment<wmma::matrix_b, 16, 16, 16, __nv_bfloat16, wmma::row_major> bH, bL;
                    wmma::load_matrix_sync(bH, &hHI[(jc*32 + ks*16)*32 + nt*16], 32);
                    wmma::load_matrix_sync(bL, &hLO[(jc*32 + ks*16)*32 + nt*16], 32);
                    wmma::mma_sync(cf[mt][nt], aH, bH, cf[mt][nt]);
                    wmma::mma_sync(cf[mt][nt], aH, bL, cf[mt][nt]);
                    wmma::mma_sync(cf[mt][nt], aL, bH, cf[mt][nt]);
                }
            }
        }
        __syncthreads();    // before next chunk overwrites P
    }

    // ---- store C, epilogue -------------------------------------------------
    #pragma unroll
    for (int mt = 0; mt < 2; ++mt) {
        if (mt >= nMt) break;
        int mrow = (wid + mt*8) * 16;
        #pragma unroll
        for (int nt = 0; nt < 2; ++nt)
            wmma::store_matrix_sync(&sC[mrow*32 + nt*16], cf[mt][nt], 32, wmma::mem_row_major);
    }
    __syncthreads();

    if (tid < N_) {
        float invl = 1.f / lv[tid];
        float inv  = bn_g[tid] * rsqrtf(bn_v[tid] + 1e-5f);
        float bb   = bn_b[tid] - bn_m[tid] * inv;
        float* dst = g_X2 + (base + tid) * FC + h*HID;
        #pragma unroll
        for (int f = 0; f < HID; f += 4) {
            float4 cv = *(float4*)&sC[tid*32 + f];
            float4 o;
            o.x = eluf(cv.x*invl) * inv + bb;
            o.y = eluf(cv.y*invl) * inv + bb;
            o.z = eluf(cv.z*invl) * inv + bb;
            o.w = eluf(cv.w*invl) * inv + bb;
            *(float4*)(dst + f) = o;
        }
    }
}

// ---------------- 4) second-stage linears, column-split over blockIdx.y ------
// y=0: pairs {sent, para, qt feats 0..13}; y=1: {qt feats 14..31}. 9 pairs each.
__global__ __launch_bounds__(256) void lin2_kernel(const float* __restrict__ Wsent,
                                                   const float* __restrict__ asent,
                                                   const float* __restrict__ Wpara,
                                                   const float* __restrict__ apara,
                                                   const float* __restrict__ Wqt,
                                                   const float* __restrict__ aqt)
{
    __shared__ __align__(16) unsigned long long Wp[256][10];  // 9 used, pad 10
    int tid = threadIdx.x;
    int which = blockIdx.y;
    for (int idx = tid; idx < 256*9; idx += 256) {
        int k = idx / 9, p = idx - k*9;
        float lo, hi;
        if (which == 0) {
            if (p == 0)      { lo = Wsent[k*2]; hi = Wsent[k*2+1]; }
            else if (p == 1) { lo = Wpara[k*2]; hi = Wpara[k*2+1]; }
            else             { int f = (p-2)*2; lo = Wqt[k*32+f]; hi = Wqt[k*32+f+1]; }
        } else {
            int f = 14 + p*2; lo = Wqt[k*32+f]; hi = Wqt[k*32+f+1];
        }
        Wp[k][p] = pack2(lo, hi);
    }
    __syncthreads();

    int row = blockIdx.x * 256 + tid;
    const float4* x4 = (const float4*)(g_X2 + (size_t)row * FC);

    unsigned long long acc2[9];
    #pragma unroll
    for (int p = 0; p < 9; ++p) acc2[p] = 0ull;

    #pragma unroll 4
    for (int kc = 0; kc < 64; ++kc) {
        float4 xv = x4[kc];
        float xs[4] = {xv.x, xv.y, xv.z, xv.w};
        #pragma unroll
        for (int q = 0; q < 4; ++q) {
            int k = kc*4 + q;
            unsigned long long xx = pack2(xs[q], xs[q]);
            const unsigned long long* wr = &Wp[k][0];
            #pragma unroll
            for (int p = 0; p < 9; ++p) fma2(acc2[p], xx, wr[p]);
        }
    }

    float c[18];
    #pragma unroll
    for (int p = 0; p < 9; ++p) {
        float2 u = unpack2(acc2[p]);
        c[2*p] = u.x; c[2*p+1] = u.y;
    }

    if (which == 0) {
        *(float2*)(g_hs + (size_t)row*2) = make_float2(c[0], c[1]);
        g_s1s[row] = c[0]*asent[0] + c[1]*asent[1];
        g_s2s[row] = c[0]*asent[2] + c[1]*asent[3];
        *(float2*)(g_hp + (size_t)row*2) = make_float2(c[2], c[3]);
        g_s1p[row] = c[2]*apara[0] + c[3]*apara[1];
        g_s2p[row] = c[2]*apara[2] + c[3]*apara[3];
        float s1q = 0.f, s2q = 0.f;
        #pragma unroll
        for (int f = 0; f < 14; ++f) {
            float v = c[4+f];
            s1q += v * aqt[f];
            s2q += v * aqt[32+f];
        }
        float* hq = g_hq + (size_t)row * HID;
        *(float4*)(hq + 0) = make_float4(c[4], c[5], c[6], c[7]);
        *(float4*)(hq + 4) = make_float4(c[8], c[9], c[10], c[11]);
        *(float2*)(hq + 8+4) = make_float2(c[16], c[17]);
        // careful: feats 8..11 were c[12..15]
        *(float4*)(hq + 8) = make_float4(c[12], c[13], c[14], c[15]);
        *(float2*)(hq + 12) = make_float2(c[16], c[17]);
        g_s1qa[row] = s1q;
        g_s2qa[row] = s2q;
    } else {
        float s1q = 0.f, s2q = 0.f;
        #pragma unroll
        for (int f = 0; f < 18; ++f) {
            float v = c[f];
            s1q += v * aqt[14+f];
            s2q += v * aqt[32+14+f];
        }
        float* hq = g_hq + (size_t)row * HID;
        *(float2*)(hq + 14) = make_float2(c[0], c[1]);
        *(float4*)(hq + 16) = make_float4(c[2], c[3], c[4], c[5]);
        *(float4*)(hq + 20) = make_float4(c[6], c[7], c[8], c[9]);
        *(float4*)(hq + 24) = make_float4(c[10], c[11], c[12], c[13]);
        *(float4*)(hq + 28) = make_float4(c[14], c[15], c[16], c[17]);
        g_s1qb[row] = s1q;
        g_s2qb[row] = s2q;
    }
}

// ---------------- 5) final attentions: y==0 -> sent+qtype, y==1 -> para ------
__global__ __launch_bounds__(256) void attn2_kernel(const float* __restrict__ W2,
                                                    float* __restrict__ out)
{
    int b = blockIdx.x, which = blockIdx.y, tid = threadIdx.x;
    __shared__ float s1a[N_], s2a[N_];
    __shared__ float ha[N_*2];
    __shared__ unsigned shm[N_*7];
    __shared__ float eq[256];
    __shared__ float h0[HID];
    __shared__ float red[2];
    size_t base = (size_t)b * N_;

    const float* gs1 = which ? g_s1p : g_s1s;
    const float* gs2 = which ? g_s2p : g_s2s;
    const float* gh  = which ? g_hp  : g_hs;

    for (int idx = tid; idx < N_; idx += 256) {
        s1a[idx] = gs1[base+idx]; s2a[idx] = gs2[base+idx];
    }
    for (int idx = tid; idx < N_*2; idx += 256)
        ha[idx] = gh[base*2+idx];
    for (int idx = tid; idx < N_*7; idx += 256)
        shm[idx] = g_mask[(base + idx/7)*8 + idx%7];
    __syncthreads();

    int i = tid;
    if (i < N_) {
        const unsigned* mrow = &shm[i*7];
        float a1 = s1a[i];
        float ms = -3.4e38f;
        for (int j = 0; j < N_; ++j) {
            int bit = (mrow[j>>5] >> (j&31)) & 1;
            float ts = lrelu(a1 + s2a[j]); ts = bit ? ts : NEGINF;
            ms = fmaxf(ms, ts);
        }
        float ls = 0.f, a0 = 0.f, o1v = 0.f;
        for (int j = 0; j < N_; ++j) {
            int bit = (mrow[j>>5] >> (j&31)) & 1;
            float ts = lrelu(a1 + s2a[j]); ts = bit ? ts : NEGINF;
            float ps = __expf(ts - ms); ls += ps;
            a0 += ps*ha[j*2]; o1v += ps*ha[j*2+1];
        }
        float o0 = a0/ls, o1 = o1v/ls;
        if (which == 0) {
            out[(base+i)*2+0] = 1.f/(1.f+__expf(-o0));
            out[(base+i)*2+1] = 1.f/(1.f+__expf(-o1));
        } else {
            out[102400 + (base+i)*2+0] = eluf(o0);
            out[102400 + (base+i)*2+1] = eluf(o1);
        }
    }

    if (which != 0) return;

    float s1q0 = g_s1qa[base] + g_s1qb[base];
    if (tid < N_) {
        int bit = (shm[tid>>5] >> (tid&31)) & 1;
        float s2q = g_s2qa[base + tid] + g_s2qb[base + tid];
        float t = lrelu(s1q0 + s2q);
        eq[tid] = bit ? t : NEGINF;
    } else eq[tid] = -3.4e38f;
    __syncthreads();
    if (tid < 32) {
        float v = -3.4e38f;
        for (int j = tid; j < N_; j += 32) v = fmaxf(v, eq[j]);
        #pragma unroll
        for (int o = 16; o; o >>= 1) v = fmaxf(v, __shfl_xor_sync(0xffffffffu, v, o));
        if (tid == 0) red[0] = v;
    }
    __syncthreads();
    float mq = red[0];
    if (tid < N_) eq[tid] = __expf(eq[tid] - mq);
    __syncthreads();
    if (tid < 32) {
        float v = 0.f;
        for (int j = tid; j < N_; j += 32) v += eq[j];
        #pragma unroll
        for (int o = 16; o; o >>= 1) v += __shfl_xor_sync(0xffffffffu, v, o);
        if (tid == 0) red[1] = v;
    }
    __syncthreads();
    float lq = red[1];
    if (tid < 32) {
        float acc = 0.f;
        for (int j = 0; j < N_; ++j) acc += eq[j] * g_hq[(base + j)*HID + tid];
        h0[tid] = acc / lq;
    }
    __syncthreads();
    if (tid < 2) {
        float s = 0.f;
        #pragma unroll
        for (int f = 0; f < HID; ++f) s += h0[f] * W2[f*2 + tid];
        out[204800 + b*2 + tid] = eluf(s);
    }
}

// ---------------------------------------------------------------------------
extern "C" void kernel_launch(void* const* d_in, const int* in_sizes, int n_in,
                              void* d_out, int out_size)
{
    const float* feat  = (const float*)d_in[0];
    const int*   adj   = (const int*)  d_in[1];
    const float* Wh    = (const float*)d_in[2];
    const float* ah    = (const float*)d_in[3];
    const float* Wsent = (const float*)d_in[4];
    const float* asent = (const float*)d_in[5];
    const float* Wpara = (const float*)d_in[6];
    const float* apara = (const float*)d_in[7];
    const float* Wqt   = (const float*)d_in[8];
    const float* aqt   = (const float*)d_in[9];
    const float* W2    = (const float*)d_in[10];
    const float* bn_g  = (const float*)d_in[11];
    const float* bn_b  = (const float*)d_in[12];
    const float* bn_m  = (const float*)d_in[13];
    const float* bn_v  = (const float*)d_in[14];
    float* out = (float*)d_out;

    cudaFuncSetAttribute(attn1_kernel,
                         cudaFuncAttributeMaxDynamicSharedMemorySize, A1_SMEM);

    mask_kernel<<<ROWS*32/256, 256>>>(adj);
    wcvt_kernel<<<FIN, 256>>>(Wh);
    gemm1_mma_kernel<<<dim3(2, 400), 256>>>(feat);
    attn1_kernel<<<B_*NH, 256, A1_SMEM>>>(ah, bn_g, bn_b, bn_m, bn_v);
    lin2_kernel<<<dim3(ROWS/256, 2), 256>>>(Wsent, asent, Wpara, apara, Wqt, aqt);
    attn2_kernel<<<dim3(B_, 2), 256>>>(W2, out);
}